// round 11
// baseline (speedup 1.0000x reference)
#include <cuda_runtime.h>
#include <cuda_fp16.h>
#include <cstdint>

// ---------------------------------------------------------------------------
// Fixed problem shape
// ---------------------------------------------------------------------------
#define TDIM 2048
#define CDIM 512
#define BH   32            // B*H
#define TOK  16384         // B*T
#define QKVN 6144          // 3*H*C
#define HC   2048          // H*C
#define SCALE_F 0.08838834764831845f   // 1/sqrt(128)

typedef __half fp16;

// ---------------------------------------------------------------------------
// Scratch (static device arrays; no cudaMalloc allowed)
// A-side operands: fp16 (hi, lo) pairs. B-side operands: single fp16.
// ---------------------------------------------------------------------------
__device__ fp16 xs_hi [(size_t)TOK * CDIM];
__device__ fp16 xs_lo [(size_t)TOK * CDIM];
__device__ fp16 ws_h  [(size_t)QKVN * CDIM];     // qkv_w, fp16
__device__ fp16 pws_h [(size_t)CDIM * HC];       // proj_w, fp16

__device__ fp16 q_hi [(size_t)BH * TDIM * CDIM]; // [bh][t][c], SCALE folded in
__device__ fp16 q_lo [(size_t)BH * TDIM * CDIM];
__device__ fp16 k_h  [(size_t)BH * TDIM * CDIM]; // [bh][t][c]
__device__ fp16 vt_h [(size_t)BH * CDIM * TDIM]; // [bh][c][t]

__device__ float g_s [(size_t)BH * TDIM * TDIM]; // scores (scaled), fp32
__device__ fp16 p_hi [(size_t)BH * TDIM * TDIM]; // softmax(S)
__device__ fp16 p_lo [(size_t)BH * TDIM * TDIM];

__device__ fp16 a_hi [(size_t)TOK * HC];         // attn out, proj layout
__device__ fp16 a_lo [(size_t)TOK * HC];

// ---------------------------------------------------------------------------
// CTA tile 128m x 256n, BK=32, 256 threads, warp grid 2(m) x 4(n),
// warp tile 64x64. 1 CTA/SM.
// Smem: NS=4 stages x (A_hi | A_lo | B) tiles, rows padded to 40 fp16 (80B).
// A tile 128 rows, B tile 256 rows.
// ---------------------------------------------------------------------------
#define ROWPAD 40
#define TILE_A (128 * ROWPAD * 2)         // 10240
#define TILE_B (256 * ROWPAD * 2)         // 20480
#define STAGE_BYTES (2 * TILE_A + TILE_B) // 40960
#define NS 4
#define SMEM_BYTES (NS * STAGE_BYTES)     // 163840

#define OFF_AHI 0
#define OFF_ALO TILE_A
#define OFF_B   (2 * TILE_A)

// ---------------------------------------------------------------------------
// PTX helpers (base sm_80-class; no 'a'-suffix features)
// ---------------------------------------------------------------------------
__device__ __forceinline__ uint32_t smem_u32(const void* p) {
    uint32_t a;
    asm("{ .reg .u64 t; cvta.to.shared.u64 t, %1; cvt.u32.u64 %0, t; }" : "=r"(a) : "l"(p));
    return a;
}
__device__ __forceinline__ void cpa16(uint32_t dst, const void* src) {
    asm volatile("cp.async.ca.shared.global [%0], [%1], 16;" :: "r"(dst), "l"(src));
}
__device__ __forceinline__ void cp_commit() {
    asm volatile("cp.async.commit_group;" ::: "memory");
}
template <int N>
__device__ __forceinline__ void cp_wait() {
    asm volatile("cp.async.wait_group %0;" :: "n"(N) : "memory");
}
__device__ __forceinline__ void ldsm4(uint32_t* r, uint32_t addr) {
    asm volatile("ldmatrix.sync.aligned.m8n8.x4.shared.b16 {%0,%1,%2,%3}, [%4];"
                 : "=r"(r[0]), "=r"(r[1]), "=r"(r[2]), "=r"(r[3]) : "r"(addr));
}
__device__ __forceinline__ void mma_f16(float* c, const uint32_t* a, const uint32_t* b) {
    asm volatile("mma.sync.aligned.m16n8k16.row.col.f32.f16.f16.f32 "
                 "{%0,%1,%2,%3}, {%4,%5,%6,%7}, {%8,%9}, {%0,%1,%2,%3};"
                 : "+f"(c[0]), "+f"(c[1]), "+f"(c[2]), "+f"(c[3])
                 : "r"(a[0]), "r"(a[1]), "r"(a[2]), "r"(a[3]), "r"(b[0]), "r"(b[1]));
}
__device__ __forceinline__ void split2(float x, fp16& h, fp16& l) {
    h = __float2half_rn(x);
    l = __float2half_rn(x - __half2float(h));
}

// ---------------------------------------------------------------------------
// Elementwise fp32 -> (hi, lo) fp16 splitter
// ---------------------------------------------------------------------------
__global__ __launch_bounds__(256)
void split_k(const float* __restrict__ src, fp16* __restrict__ hi,
             fp16* __restrict__ lo, size_t n)
{
    size_t i = ((size_t)blockIdx.x * 256 + threadIdx.x) * 4;
    if (i >= n) return;
    float4 v = *(const float4*)(src + i);
    __half2 h0, h1, l0, l1;
    split2(v.x, h0.x, l0.x);
    split2(v.y, h0.y, l0.y);
    split2(v.z, h1.x, l1.x);
    split2(v.w, h1.y, l1.y);
    *(__half2*)(hi + i)     = h0;
    *(__half2*)(hi + i + 2) = h1;
    *(__half2*)(lo + i)     = l0;
    *(__half2*)(lo + i + 2) = l1;
}

// Elementwise fp32 -> fp16 cast (for B-side weights)
__global__ __launch_bounds__(256)
void cast_k(const float* __restrict__ src, fp16* __restrict__ dst, size_t n)
{
    size_t i = ((size_t)blockIdx.x * 256 + threadIdx.x) * 4;
    if (i >= n) return;
    float4 v = *(const float4*)(src + i);
    __half2 h0 = __floats2half2_rn(v.x, v.y);
    __half2 h1 = __floats2half2_rn(v.z, v.w);
    *(__half2*)(dst + i)     = h0;
    *(__half2*)(dst + i + 2) = h1;
}

// ---------------------------------------------------------------------------
// fp16 A-split 2-term GEMM, cp.async 4-stage pipeline, CTA tile 128x256.
//  MODE 0: QKV : xs[16384,512] @ ws[6144,512]^T -> q(hi/lo,*SCALE)/k/vt
//  MODE 1: S   : q[T,512] @ k[T,512]^T          -> g_s fp32  (z = head)
//  MODE 2: O   : p[T,T]  @ vt[512,2048]^T       -> a hi/lo   (z = head)
//  MODE 3: PROJ: a[16384,2048] @ pws[512,2048]^T + bias -> out fp32
// ---------------------------------------------------------------------------
template <int MODE>
__global__ __launch_bounds__(256, 1)
void mgemm(float* __restrict__ OUT, const float* __restrict__ bias)
{
    constexpr int K = (MODE <= 1) ? CDIM : TDIM;   // MODE3 uses HC=2048=TDIM
    constexpr int NITER = K / 32;

    extern __shared__ char smc[];
    const uint32_t sb = smem_u32(smc);

    const int tid  = threadIdx.x;
    const int wid  = tid >> 5;
    const int lane = tid & 31;
    const int wm   = wid & 1;       // 0..1 -> m offset *64
    const int wn   = wid >> 1;      // 0..3 -> n offset *64
    const int m0   = blockIdx.y * 128;
    const int n0   = blockIdx.x * 256;
    const size_t z = blockIdx.z;

    const fp16 *Ah, *Al, *Bh;
    if (MODE == 0)      { Ah = xs_hi;  Al = xs_lo;  Bh = ws_h; }
    else if (MODE == 1) {
        Ah = q_hi + z * (size_t)TDIM * CDIM; Al = q_lo + z * (size_t)TDIM * CDIM;
        Bh = k_h + z * (size_t)TDIM * CDIM;
    } else if (MODE == 2) {
        Ah = p_hi + z * (size_t)TDIM * TDIM; Al = p_lo + z * (size_t)TDIM * TDIM;
        Bh = vt_h + z * (size_t)CDIM * TDIM;
    } else              { Ah = a_hi;  Al = a_lo;  Bh = pws_h; }

    // A loader: 128 rows, 2 threads/row, 32B each (2 cpa16 per tile)
    const int lr = tid >> 1;
    const int lh = (tid & 1) * 16;
    const fp16* agh = Ah + (size_t)(m0 + lr) * K + lh;
    const fp16* agl = Al + (size_t)(m0 + lr) * K + lh;
    const uint32_t adst = sb + (uint32_t)((lr * ROWPAD + lh) * 2);
    // B loader: 256 rows, 1 thread/row, 64B (4 cpa16)
    const fp16* bg = Bh + (size_t)(n0 + tid) * K;
    const uint32_t bdst = sb + (uint32_t)(OFF_B + tid * ROWPAD * 2);

#define ISSUE_STAGE(kt, buf) do {                                             \
        const int _k0 = (kt) * 32;                                            \
        const uint32_t _o = (uint32_t)((buf) * STAGE_BYTES);                  \
        cpa16(adst + _o + OFF_AHI,      agh + _k0);                           \
        cpa16(adst + _o + OFF_AHI + 16, agh + _k0 + 8);                       \
        cpa16(adst + _o + OFF_ALO,      agl + _k0);                           \
        cpa16(adst + _o + OFF_ALO + 16, agl + _k0 + 8);                       \
        cpa16(bdst + _o,      bg + _k0);                                      \
        cpa16(bdst + _o + 16, bg + _k0 + 8);                                  \
        cpa16(bdst + _o + 32, bg + _k0 + 16);                                 \
        cpa16(bdst + _o + 48, bg + _k0 + 24);                                 \
    } while (0)

    float acc[4][8][4];
#pragma unroll
    for (int i = 0; i < 4; i++)
#pragma unroll
        for (int j = 0; j < 8; j++)
#pragma unroll
            for (int c = 0; c < 4; c++) acc[i][j][c] = 0.f;

    // prologue: stages 0 .. NS-2
#pragma unroll
    for (int s = 0; s < NS - 1; s++) {
        ISSUE_STAGE(s, s);
        cp_commit();
    }

    for (int it = 0; it < NITER; ++it) {
        cp_wait<NS - 2>();          // stage `it` resident
        __syncthreads();            // all warps done reading stage it-1

        if (it + NS - 1 < NITER) {  // refill buffer consumed at it-1
            ISSUE_STAGE(it + NS - 1, (it + NS - 1) % NS);
            cp_commit();
        }

        const uint32_t stage = sb + (uint32_t)((it % NS) * STAGE_BYTES);
#pragma unroll
        for (int ks = 0; ks < 2; ks++) {
            // A fragments: 4 m-tiles x (hi, lo); 16m x 16k each (ldsm x4)
            uint32_t ah[4][4], al[4][4];
            const int arow  = wm * 64 + (lane & 15);
            const int akoff = ks * 16 + (lane >> 4) * 8;
#pragma unroll
            for (int mt = 0; mt < 4; mt++) {
                const uint32_t ao = stage + (uint32_t)(((arow + mt * 16) * ROWPAD + akoff) * 2);
                ldsm4(ah[mt], ao + OFF_AHI);
                ldsm4(al[mt], ao + OFF_ALO);
            }
            // B fragments: 8 n-tiles as 4 x4-ldmatrix pairs (16n x 16k each)
            uint32_t bq[8][2];
            const int brow  = wn * 64 + (lane & 7) + ((lane >> 4) & 1) * 8;
            const int bkoff = ks * 16 + ((lane >> 3) & 1) * 8;
#pragma unroll
            for (int pr = 0; pr < 4; pr++) {
                uint32_t r4[4];
                const uint32_t bo = stage + (uint32_t)(OFF_B + ((brow + pr * 16) * ROWPAD + bkoff) * 2);
                ldsm4(r4, bo);
                bq[pr * 2 + 0][0] = r4[0];
                bq[pr * 2 + 0][1] = r4[1];
                bq[pr * 2 + 1][0] = r4[2];
                bq[pr * 2 + 1][1] = r4[3];
            }
#pragma unroll
            for (int mt = 0; mt < 4; mt++) {
#pragma unroll
                for (int nt = 0; nt < 8; nt++) {
                    mma_f16(acc[mt][nt], ah[mt], bq[nt]);
                    mma_f16(acc[mt][nt], al[mt], bq[nt]);
                }
            }
        }
    }
#undef ISSUE_STAGE

    // ------------------------------------------------------------- epilogue
    const int g   = lane >> 2;
    const int tig = lane & 3;

#pragma unroll
    for (int mt = 0; mt < 4; mt++) {
#pragma unroll
        for (int nt = 0; nt < 8; nt++) {
            const int r0 = m0 + wm * 64 + mt * 16 + g;
            const int c0 = n0 + wn * 64 + nt * 8 + tig * 2;
            float* ac = acc[mt][nt];

            if (MODE == 0) {
                // 256-wide tile never crosses a 512 (head) or 2048 (s) boundary
                const int s = n0 >> 11;            // 0:q 1:k 2:v
                const int h = (n0 >> 9) & 3;
                const int cc = c0 & 511;
                const int b = m0 >> 11;
                const int t = r0 & 2047;
                const size_t head = (size_t)(b * 4 + h);
                if (s == 0) {                      // q: scaled hi/lo
                    __half2 h0, h1, l0, l1;
                    split2(ac[0] * SCALE_F, h0.x, l0.x);
                    split2(ac[1] * SCALE_F, h0.y, l0.y);
                    split2(ac[2] * SCALE_F, h1.x, l1.x);
                    split2(ac[3] * SCALE_F, h1.y, l1.y);
                    fp16* dh = q_hi + (head * TDIM + t) * CDIM + cc;
                    fp16* dl = q_lo + (head * TDIM + t) * CDIM + cc;
                    *(__half2*)dh = h0;
                    *(__half2*)dl = l0;
                    *(__half2*)(dh + 8 * CDIM) = h1;
                    *(__half2*)(dl + 8 * CDIM) = l1;
                } else if (s == 1) {               // k: single fp16
                    fp16* dh = k_h + (head * TDIM + t) * CDIM + cc;
                    *(__half2*)dh = __floats2half2_rn(ac[0], ac[1]);
                    *(__half2*)(dh + 8 * CDIM) = __floats2half2_rn(ac[2], ac[3]);
                } else {                           // v: transposed single fp16
                    fp16* vb = vt_h + head * (size_t)CDIM * TDIM;
                    vb[(size_t)(cc + 0) * TDIM + t]     = __float2half_rn(ac[0]);
                    vb[(size_t)(cc + 1) * TDIM + t]     = __float2half_rn(ac[1]);
                    vb[(size_t)(cc + 0) * TDIM + t + 8] = __float2half_rn(ac[2]);
                    vb[(size_t)(cc + 1) * TDIM + t + 8] = __float2half_rn(ac[3]);
                }
            } else if (MODE == 1) {
                float* p0 = g_s + z * (size_t)TDIM * TDIM + (size_t)r0 * TDIM + c0;
                *(float2*)p0 = make_float2(ac[0], ac[1]);
                *(float2*)(p0 + 8 * TDIM) = make_float2(ac[2], ac[3]);
            } else if (MODE == 2) {
                const int b = (int)z >> 2;
                const int h = (int)z & 3;
                __half2 h0, h1, l0, l1;
                split2(ac[0], h0.x, l0.x);
                split2(ac[1], h0.y, l0.y);
                split2(ac[2], h1.x, l1.x);
                split2(ac[3], h1.y, l1.y);
                const size_t off = ((size_t)(b * TDIM + r0)) * HC + h * CDIM + c0;
                *(__half2*)(a_hi + off) = h0;
                *(__half2*)(a_lo + off) = l0;
                *(__half2*)(a_hi + off + 8 * HC) = h1;
                *(__half2*)(a_lo + off + 8 * HC) = l1;
            } else {
                const float2 bi = *(const float2*)(bias + c0);
                float* p0 = OUT + (size_t)r0 * CDIM + c0;
                *(float2*)p0 = make_float2(ac[0] + bi.x, ac[1] + bi.y);
                *(float2*)(p0 + 8 * CDIM) = make_float2(ac[2] + bi.x, ac[3] + bi.y);
            }
        }
    }
}

// ---------------------------------------------------------------------------
// Row softmax over g_s -> (p_hi, p_lo). One block per row of 2048.
// ---------------------------------------------------------------------------
__global__ __launch_bounds__(256)
void softmax_k()
{
    const size_t row = blockIdx.x;
    const float* p = g_s + row * TDIM;
    fp16* ph = p_hi + row * TDIM;
    fp16* pl = p_lo + row * TDIM;
    const int tid = threadIdx.x;

    __shared__ float red[256];

    float v[8];
    float m = -1e30f;
#pragma unroll
    for (int i = 0; i < 8; i++) {
        v[i] = p[tid + i * 256];
        m = fmaxf(m, v[i]);
    }
    red[tid] = m;
    __syncthreads();
#pragma unroll
    for (int s = 128; s > 0; s >>= 1) {
        if (tid < s) red[tid] = fmaxf(red[tid], red[tid + s]);
        __syncthreads();
    }
    m = red[0];
    __syncthreads();

    float sum = 0.f;
#pragma unroll
    for (int i = 0; i < 8; i++) {
        v[i] = expf(v[i] - m);
        sum += v[i];
    }
    red[tid] = sum;
    __syncthreads();
#pragma unroll
    for (int s = 128; s > 0; s >>= 1) {
        if (tid < s) red[tid] += red[tid + s];
        __syncthreads();
    }
    const float inv = 1.f / red[0];
#pragma unroll
    for (int i = 0; i < 8; i++) {
        fp16 h, l;
        split2(v[i] * inv, h, l);
        ph[tid + i * 256] = h;
        pl[tid + i * 256] = l;
    }
}

// ---------------------------------------------------------------------------
// kernel_launch: graph-capturable launches, no allocations.
// ---------------------------------------------------------------------------
extern "C" void kernel_launch(void* const* d_in, const int* in_sizes, int n_in,
                              void* d_out, int out_size)
{
    const float* x      = (const float*)d_in[0];
    const float* qkv_w  = (const float*)d_in[1];
    const float* proj_w = (const float*)d_in[2];
    const float* proj_b = (const float*)d_in[3];
    float* out = (float*)d_out;
    (void)in_sizes; (void)n_in; (void)out_size;

    cudaFuncSetAttribute(mgemm<0>, cudaFuncAttributeMaxDynamicSharedMemorySize, SMEM_BYTES);
    cudaFuncSetAttribute(mgemm<1>, cudaFuncAttributeMaxDynamicSharedMemorySize, SMEM_BYTES);
    cudaFuncSetAttribute(mgemm<2>, cudaFuncAttributeMaxDynamicSharedMemorySize, SMEM_BYTES);
    cudaFuncSetAttribute(mgemm<3>, cudaFuncAttributeMaxDynamicSharedMemorySize, SMEM_BYTES);

    fp16 *d_xs_hi, *d_xs_lo, *d_ws, *d_pws;
    cudaGetSymbolAddress((void**)&d_xs_hi, xs_hi);
    cudaGetSymbolAddress((void**)&d_xs_lo, xs_lo);
    cudaGetSymbolAddress((void**)&d_ws,    ws_h);
    cudaGetSymbolAddress((void**)&d_pws,   pws_h);

    dim3 blk(256);

    // 0) prepare operands: x -> hi/lo split; weights -> fp16 cast
    const size_t nx = (size_t)TOK * CDIM, nw = (size_t)QKVN * CDIM, np = (size_t)CDIM * HC;
    split_k<<<(unsigned)((nx / 4 + 255) / 256), blk>>>(x, d_xs_hi, d_xs_lo, nx);
    cast_k <<<(unsigned)((nw / 4 + 255) / 256), blk>>>(qkv_w,  d_ws,  nw);
    cast_k <<<(unsigned)((np / 4 + 255) / 256), blk>>>(proj_w, d_pws, np);

    // 1) QKV projection -> q (scaled hi/lo), k, vt
    mgemm<0><<<dim3(QKVN / 256, TOK / 128, 1), blk, SMEM_BYTES>>>(nullptr, nullptr);
    // 2) S = Q K^T (scale pre-folded)
    mgemm<1><<<dim3(TDIM / 256, TDIM / 128, BH), blk, SMEM_BYTES>>>(nullptr, nullptr);
    // 3) softmax rows -> p hi/lo
    softmax_k<<<BH * TDIM, 256>>>();
    // 4) O = P V -> a hi/lo (proj-ready layout)
    mgemm<2><<<dim3(CDIM / 256, TDIM / 128, BH), blk, SMEM_BYTES>>>(nullptr, nullptr);
    // 5) final projection + bias -> out
    mgemm<3><<<dim3(CDIM / 256, TOK / 128, 1), blk, SMEM_BYTES>>>(out, proj_b);
}